// round 11
// baseline (speedup 1.0000x reference)
#include <cuda_runtime.h>
#include <cuda_fp16.h>
#include <math.h>
#include <stdint.h>

#define NE      8
#define TOPK    2
#define HID     1024
#define INTERN  4096
#define TTOK    8192
#define CAP     2560
#define ECAP    (NE*CAP)

// ---------------- scratch (static device globals) ----------------
__device__ int      g_src_token[ECAP];
__device__ int      g_slot[TTOK * TOPK];
__device__ int      g_count[NE];
__device__ __half   g_xhi[(size_t)TTOK * HID];
__device__ __half   g_gupT_hi[(size_t)NE * 2 * INTERN * HID];  // [e][n][k]
__device__ __half   g_dpT_hi[(size_t)NE * HID * INTERN];       // [e][n][k]
__device__ __half   g_inter_hi[(size_t)ECAP * INTERN];
__device__ float    g_eo[(size_t)ECAP * HID];

// ---------------- helpers ----------------
__device__ __forceinline__ uint32_t smem_u32(const void* p) {
    uint32_t a;
    asm("{ .reg .u64 t; cvta.to.shared.u64 t, %1; cvt.u32.u64 %0, t; }" : "=r"(a) : "l"(p));
    return a;
}
__device__ __forceinline__ void mma_f16(float* d, const uint32_t* a, const uint32_t* b) {
    asm volatile(
        "mma.sync.aligned.m16n8k16.row.col.f32.f16.f16.f32 "
        "{%0,%1,%2,%3}, {%4,%5,%6,%7}, {%8,%9}, {%0,%1,%2,%3};"
        : "+f"(d[0]), "+f"(d[1]), "+f"(d[2]), "+f"(d[3])
        : "r"(a[0]), "r"(a[1]), "r"(a[2]), "r"(a[3]), "r"(b[0]), "r"(b[1]));
}
__device__ __forceinline__ void ldm4(uint32_t* r, uint32_t addr) {
    asm volatile("ldmatrix.sync.aligned.m8n8.x4.shared.b16 {%0,%1,%2,%3}, [%4];"
        : "=r"(r[0]), "=r"(r[1]), "=r"(r[2]), "=r"(r[3]) : "r"(addr));
}
__device__ __forceinline__ void cp8(uint32_t dst, const void* src, uint32_t sz) {
    asm volatile("cp.async.ca.shared.global [%0], [%1], 8, %2;"
        :: "r"(dst), "l"(src), "r"(sz) : "memory");
}
#define CP_COMMIT() asm volatile("cp.async.commit_group;" ::: "memory")
#define CP_WAIT1()  asm volatile("cp.async.wait_group 1;" ::: "memory")
#define CP_WAIT0()  asm volatile("cp.async.wait_group 0;" ::: "memory")

__device__ __forceinline__ uint32_t hpack(__half a, __half b) {
    return (uint32_t)__half_as_ushort(a) | ((uint32_t)__half_as_ushort(b) << 16);
}

// SMEM geometry: rows padded to 72 halves (144B), conflict-free (verified R3-R8).
#define ROWB    144
#define ST1_SZ  36864            // gemm1 stage: A(128) + Bgh(64) + Buh(64) rows
#define SM1_SZ  (3 * ST1_SZ)     // 110592 -> 2 CTAs/SM
#define ST2_SZ  36864            // gemm2 stage: A(128) + Bh(128) rows
#define SM2_SZ  (3 * ST2_SZ)     // 110592 -> 2 CTAs/SM

// ---------------------------------------------------------------------------
// Routing + per-expert counts
// ---------------------------------------------------------------------------
__global__ void routing_kernel(const int* __restrict__ expert_index) {
    const int e    = threadIdx.x >> 5;
    const int lane = threadIdx.x & 31;
    int count = 0;
    for (int base = 0; base < TTOK; base += 32) {
        const int t = base + lane;
        const int2 ei = ((const int2*)expert_index)[t];
        int k = -1;
        if (ei.x == e) k = 0;
        else if (ei.y == e) k = 1;
        const unsigned m = __ballot_sync(0xffffffffu, k >= 0);
        if (k >= 0) {
            const int pos = count + __popc(m & ((1u << lane) - 1u));
            if (pos < CAP) {
                g_src_token[e * CAP + pos] = t;
                g_slot[t * TOPK + k] = e * CAP + pos;
            } else {
                g_slot[t * TOPK + k] = ECAP;
            }
        }
        count += __popc(m);
    }
    const int filled = count < CAP ? count : CAP;
    for (int p = filled + lane; p < CAP; p += 32)
        g_src_token[e * CAP + p] = -1;
    if (lane == 0) g_count[e] = filled;
}

// ---------------------------------------------------------------------------
// Prep: hidden states -> fp16
// ---------------------------------------------------------------------------
__global__ void split_x(const float* __restrict__ x) {
    const size_t i0 = ((size_t)blockIdx.x * 256 + threadIdx.x) * 4;
    const float4 v = *(const float4*)(x + i0);
    uint2 o;
    o.x = hpack(__float2half(v.x), __float2half(v.y));
    o.y = hpack(__float2half(v.z), __float2half(v.w));
    *(uint2*)(g_xhi + i0) = o;
}

// ---------------------------------------------------------------------------
// Prep: transposes to [e][n][k] fp16 (hi only)
// ---------------------------------------------------------------------------
__global__ void transpose_gup(const float* __restrict__ in) {
    __shared__ float tile[32][33];
    const int R = HID, C = 2 * INTERN;
    const int e  = blockIdx.z;
    const int r0 = blockIdx.y * 32, c0 = blockIdx.x * 32;
    const int tx = threadIdx.x & 31, ty = threadIdx.x >> 5;
    const size_t base = (size_t)e * R * C;
#pragma unroll
    for (int i = 0; i < 32; i += 8)
        tile[ty + i][tx] = in[base + (size_t)(r0 + ty + i) * C + c0 + tx];
    __syncthreads();
#pragma unroll
    for (int i = 0; i < 32; i += 8) {
        const float v = tile[tx][ty + i];
        g_gupT_hi[base + (size_t)(c0 + ty + i) * R + r0 + tx] = __float2half(v);
    }
}
__global__ void transpose_dp(const float* __restrict__ in) {
    __shared__ float tile[32][33];
    const int R = INTERN, C = HID;
    const int e  = blockIdx.z;
    const int r0 = blockIdx.y * 32, c0 = blockIdx.x * 32;
    const int tx = threadIdx.x & 31, ty = threadIdx.x >> 5;
    const size_t base = (size_t)e * R * C;
#pragma unroll
    for (int i = 0; i < 32; i += 8)
        tile[ty + i][tx] = in[base + (size_t)(r0 + ty + i) * C + c0 + tx];
    __syncthreads();
#pragma unroll
    for (int i = 0; i < 32; i += 8) {
        const float v = tile[tx][ty + i];
        g_dpT_hi[base + (size_t)(c0 + ty + i) * R + r0 + tx] = __float2half(v);
    }
}

// ---------------------------------------------------------------------------
// GEMM1: inter = silu(X@Wg)*(X@Wu), fp16 hi-only.
// CTA tile M=128, N=64(gate)+64(up), BK=64, single-sync 3-buffer multistage.
// 2 CTAs/SM. SMEM stage: Ah(0) Bgh(18432) Buh(27648)
// ---------------------------------------------------------------------------
__global__ __launch_bounds__(256, 2) void gemm1_mma() {
    const int e    = blockIdx.z;
    const int row0 = blockIdx.y * 128;
    if (row0 >= g_count[e]) return;          // dead-tile elimination

    extern __shared__ char smem[];
    __shared__ int s_tok[128];
    const int tid = threadIdx.x;
    const int n0  = blockIdx.x * 64;

    if (tid < 128) s_tok[tid] = g_src_token[e * CAP + row0 + tid];
    __syncthreads();
    const uint32_t sdyn = smem_u32(smem);

    auto load_stage = [&](int s, int buf) {
        const int k0 = s * 64;
        const uint32_t sd = sdyn + buf * ST1_SZ;
#pragma unroll
        for (int i = 0; i < 8; i++) {           // A hi: 128 rows x 16 cp8
            const int idx = tid + i * 256, row = idx >> 4, cc = idx & 15;
            const int tok = s_tok[row];
            const int tokc = tok < 0 ? 0 : tok;
            const uint32_t sz = tok < 0 ? 0u : 8u;
            cp8(sd + row * ROWB + cc * 8, g_xhi + (size_t)tokc * HID + k0 + cc * 4, sz);
        }
#pragma unroll
        for (int i = 0; i < 4; i++) {           // B: 64 rows x 16 cp8 x {gate,up}
            const int idx = tid + i * 256, row = idx >> 4, cc = idx & 15;
            const size_t og = ((size_t)e * 2 * INTERN + n0 + row) * HID + k0 + cc * 4;
            const size_t ou = og + (size_t)INTERN * HID;
            const uint32_t d = sd + 18432 + row * ROWB + cc * 8;
            cp8(d,        g_gupT_hi + og, 8);
            cp8(d + 9216, g_gupT_hi + ou, 8);
        }
        CP_COMMIT();
    };

    const int lane = tid & 31, wid = tid >> 5;
    const int wm = (wid & 1) * 64;
    const int wn = (wid >> 1) * 16;
    const int gq = lane >> 2, tq = lane & 3;

    float accg[4][2][4] = {}, accu[4][2][4] = {};

    const int NS = HID / 64;  // 16
    load_stage(0, 0);
    load_stage(1, 1);
    for (int s = 0; s < NS; s++) {
        if (s + 1 < NS) CP_WAIT1(); else CP_WAIT0();
        __syncthreads();
        if (s + 2 < NS) load_stage(s + 2, (s + 2) % 3);
        const int buf = s % 3;
        const uint32_t sA = sdyn + buf * ST1_SZ;
        const char*    sb = smem + buf * ST1_SZ;
#pragma unroll
        for (int ks = 0; ks < 4; ks++) {
            uint32_t ah[4][4];
#pragma unroll
            for (int i = 0; i < 4; i++) {
                const uint32_t ad = sA + (wm + i * 16 + (lane & 15)) * ROWB
                                       + (ks * 16 + ((lane >> 4) << 3)) * 2;
                ldm4(ah[i], ad);
            }
            uint32_t bg[2][2], bu[2][2];
#pragma unroll
            for (int j = 0; j < 2; j++) {
                const int boff = 18432 + (wn + j * 8 + gq) * ROWB + ks * 32 + tq * 4;
                bg[j][0] = *(const uint32_t*)(sb + boff);
                bg[j][1] = *(const uint32_t*)(sb + boff + 16);
                bu[j][0] = *(const uint32_t*)(sb + boff + 9216);
                bu[j][1] = *(const uint32_t*)(sb + boff + 9216 + 16);
            }
#pragma unroll
            for (int i = 0; i < 4; i++)
#pragma unroll
                for (int j = 0; j < 2; j++) {
                    mma_f16(accg[i][j], ah[i], bg[j]);
                    mma_f16(accu[i][j], ah[i], bu[j]);
                }
        }
    }

    // epilogue: silu(gate)*up -> fp16 direct to global
#pragma unroll
    for (int i = 0; i < 4; i++) {
        const int rg = row0 + wm + i * 16 + gq;
#pragma unroll
        for (int j = 0; j < 2; j++) {
            const int col = n0 + wn + j * 8 + 2 * tq;
#pragma unroll
            for (int h = 0; h < 2; h++) {
                const float g0 = accg[i][j][h * 2 + 0], g1 = accg[i][j][h * 2 + 1];
                const float u0 = accu[i][j][h * 2 + 0], u1 = accu[i][j][h * 2 + 1];
                const float v0 = u0 * g0 / (1.f + __expf(-g0));
                const float v1 = u1 * g1 / (1.f + __expf(-g1));
                const size_t o = ((size_t)e * CAP + rg + h * 8) * INTERN + col;
                *(uint32_t*)(g_inter_hi + o) = hpack(__float2half(v0), __float2half(v1));
            }
        }
    }
}

// ---------------------------------------------------------------------------
// GEMM2: eo = inter @ down, fp16 hi-only.
// CTA tile M=128, N=128, BK=64, single-sync 3-buffer multistage. 2 CTAs/SM.
// SMEM stage: Ah(0) Bh(18432)
// ---------------------------------------------------------------------------
__global__ __launch_bounds__(256, 2) void gemm2_mma() {
    const int e    = blockIdx.z;
    const int row0 = blockIdx.y * 128;
    if (row0 >= g_count[e]) return;          // dead-tile elimination

    extern __shared__ char smem[];
    const int tid = threadIdx.x;
    const int n0  = blockIdx.x * 128;
    const uint32_t sdyn = smem_u32(smem);

    auto load_stage = [&](int s, int buf) {
        const int k0 = s * 64;
        const uint32_t sd = sdyn + buf * ST2_SZ;
#pragma unroll
        for (int i = 0; i < 8; i++) {           // A hi: 128 rows x 16 cp8
            const int idx = tid + i * 256, row = idx >> 4, cc = idx & 15;
            const size_t oa = ((size_t)e * CAP + row0 + row) * INTERN + k0 + cc * 4;
            cp8(sd + row * ROWB + cc * 8, g_inter_hi + oa, 8);
        }
#pragma unroll
        for (int i = 0; i < 8; i++) {           // B hi: 128 rows x 16 cp8
            const int idx = tid + i * 256, row = idx >> 4, cc = idx & 15;
            const size_t ob = ((size_t)e * HID + n0 + row) * INTERN + k0 + cc * 4;
            cp8(sd + 18432 + row * ROWB + cc * 8, g_dpT_hi + ob, 8);
        }
        CP_COMMIT();
    };

    const int lane = tid & 31, wid = tid >> 5;
    const int wm = (wid & 1) * 64;
    const int wn = (wid >> 1) * 32;
    const int gq = lane >> 2, tq = lane & 3;

    float acc[4][4][4] = {};

    const int NS = INTERN / 64;  // 64
    load_stage(0, 0);
    load_stage(1, 1);
    for (int s = 0; s < NS; s++) {
        if (s + 1 < NS) CP_WAIT1(); else CP_WAIT0();
        __syncthreads();
        if (s + 2 < NS) load_stage(s + 2, (s + 2) % 3);
        const int buf = s % 3;
        const uint32_t sA = sdyn + buf * ST2_SZ;
        const char*    sb = smem + buf * ST2_SZ;
#pragma unroll
        for (int ks = 0; ks < 4; ks++) {
            uint32_t ah[4][4];
#pragma unroll
            for (int i = 0; i < 4; i++) {
                const uint32_t ad = sA + (wm + i * 16 + (lane & 15)) * ROWB
                                       + (ks * 16 + ((lane >> 4) << 3)) * 2;
                ldm4(ah[i], ad);
            }
            uint32_t bh[4][2];
#pragma unroll
            for (int j = 0; j < 4; j++) {
                const int boff = 18432 + (wn + j * 8 + gq) * ROWB + ks * 32 + tq * 4;
                bh[j][0] = *(const uint32_t*)(sb + boff);
                bh[j][1] = *(const uint32_t*)(sb + boff + 16);
            }
#pragma unroll
            for (int i = 0; i < 4; i++)
#pragma unroll
                for (int j = 0; j < 4; j++)
                    mma_f16(acc[i][j], ah[i], bh[j]);
        }
    }

#pragma unroll
    for (int i = 0; i < 4; i++) {
        const int rg = row0 + wm + i * 16 + gq;
#pragma unroll
        for (int j = 0; j < 4; j++) {
            const int col = n0 + wn + j * 8 + 2 * tq;
#pragma unroll
            for (int h = 0; h < 2; h++) {
                const size_t o = ((size_t)e * CAP + rg + h * 8) * HID + col;
                *(float2*)(g_eo + o) = make_float2(acc[i][j][h * 2], acc[i][j][h * 2 + 1]);
            }
        }
    }
}

// ---------------------------------------------------------------------------
// Combine (verified R1)
// ---------------------------------------------------------------------------
__global__ void combine_kernel(const float* __restrict__ aff,
                               const int*   __restrict__ eidx,
                               float*       __restrict__ out) {
    const int idx = blockIdx.x * 256 + threadIdx.x;
    const int t = idx >> 8;
    const int c = (idx & 255) << 2;
    const int2 ei = ((const int2*)eidx)[t];
    const float a0 = aff[t * NE + ei.x];
    const float a1 = aff[t * NE + ei.y];
    const float inv = 1.f / (a0 + a1);
    const int s0 = g_slot[t * TOPK + 0];
    const int s1 = g_slot[t * TOPK + 1];
    float4 r = make_float4(0.f, 0.f, 0.f, 0.f);
    if (s0 < ECAP) {
        const float w = a0 * inv;
        const float4 v = *(const float4*)(g_eo + (size_t)s0 * HID + c);
        r.x += w * v.x; r.y += w * v.y; r.z += w * v.z; r.w += w * v.w;
    }
    if (s1 < ECAP) {
        const float w = a1 * inv;
        const float4 v = *(const float4*)(g_eo + (size_t)s1 * HID + c);
        r.x += w * v.x; r.y += w * v.y; r.z += w * v.z; r.w += w * v.w;
    }
    *(float4*)(out + (size_t)t * HID + c) = r;
}

// ---------------------------------------------------------------------------
extern "C" void kernel_launch(void* const* d_in, const int* in_sizes, int n_in,
                              void* d_out, int out_size) {
    const float* x    = (const float*)d_in[0];
    const float* aff  = (const float*)d_in[1];
    const int*   eidx = (const int*)  d_in[2];
    const float* gup  = (const float*)d_in[3];
    const float* dp   = (const float*)d_in[4];
    float* out = (float*)d_out;

    cudaFuncSetAttribute(gemm1_mma, cudaFuncAttributeMaxDynamicSharedMemorySize, SM1_SZ);
    cudaFuncSetAttribute(gemm2_mma, cudaFuncAttributeMaxDynamicSharedMemorySize, SM2_SZ);

    routing_kernel<<<1, 256>>>(eidx);
    split_x<<<(TTOK * HID) / 1024, 256>>>(x);
    transpose_gup<<<dim3(2 * INTERN / 32, HID / 32, NE), 256>>>(gup);
    transpose_dp<<<dim3(HID / 32, INTERN / 32, NE), 256>>>(dp);
    gemm1_mma<<<dim3(INTERN / 64, CAP / 128, NE), 256, SM1_SZ>>>();
    gemm2_mma<<<dim3(HID / 128, CAP / 128, NE), 256, SM2_SZ>>>();
    combine_kernel<<<(TTOK * (HID / 4)) / 256, 256>>>(aff, eidx, out);
}

// round 12
// speedup vs baseline: 1.0080x; 1.0080x over previous
#include <cuda_runtime.h>
#include <cuda_fp16.h>
#include <math.h>
#include <stdint.h>

#define NE      8
#define TOPK    2
#define HID     1024
#define INTERN  4096
#define TTOK    8192
#define CAP     2560
#define ECAP    (NE*CAP)

// ---------------- scratch (static device globals) ----------------
__device__ int      g_src_token[ECAP];
__device__ int      g_slot[TTOK * TOPK];
__device__ int      g_count[NE];
__device__ __half   g_xhi[(size_t)TTOK * HID];
__device__ __half   g_gupT_hi[(size_t)NE * 2 * INTERN * HID];  // [e][n][k]
__device__ __half   g_dpT_hi[(size_t)NE * HID * INTERN];       // [e][n][k]
__device__ __half   g_inter_hi[(size_t)ECAP * INTERN];
__device__ float    g_eo[(size_t)ECAP * HID];

// ---------------- helpers ----------------
__device__ __forceinline__ uint32_t smem_u32(const void* p) {
    uint32_t a;
    asm("{ .reg .u64 t; cvta.to.shared.u64 t, %1; cvt.u32.u64 %0, t; }" : "=r"(a) : "l"(p));
    return a;
}
__device__ __forceinline__ void mma_f16(float* d, const uint32_t* a, const uint32_t* b) {
    asm volatile(
        "mma.sync.aligned.m16n8k16.row.col.f32.f16.f16.f32 "
        "{%0,%1,%2,%3}, {%4,%5,%6,%7}, {%8,%9}, {%0,%1,%2,%3};"
        : "+f"(d[0]), "+f"(d[1]), "+f"(d[2]), "+f"(d[3])
        : "r"(a[0]), "r"(a[1]), "r"(a[2]), "r"(a[3]), "r"(b[0]), "r"(b[1]));
}
__device__ __forceinline__ void ldm4(uint32_t* r, uint32_t addr) {
    asm volatile("ldmatrix.sync.aligned.m8n8.x4.shared.b16 {%0,%1,%2,%3}, [%4];"
        : "=r"(r[0]), "=r"(r[1]), "=r"(r[2]), "=r"(r[3]) : "r"(addr));
}
__device__ __forceinline__ void cp8(uint32_t dst, const void* src, uint32_t sz) {
    asm volatile("cp.async.ca.shared.global [%0], [%1], 8, %2;"
        :: "r"(dst), "l"(src), "r"(sz) : "memory");
}
#define CP_COMMIT() asm volatile("cp.async.commit_group;" ::: "memory")
#define CP_WAIT1()  asm volatile("cp.async.wait_group 1;" ::: "memory")
#define CP_WAIT0()  asm volatile("cp.async.wait_group 0;" ::: "memory")

__device__ __forceinline__ uint32_t hpack(__half a, __half b) {
    return (uint32_t)__half_as_ushort(a) | ((uint32_t)__half_as_ushort(b) << 16);
}

// SMEM geometry: rows padded to 72 halves (144B), conflict-free (verified R3-R8).
#define ROWB    144
#define ST1_SZ  36864            // gemm1 stage: A(128) + Bgh(64) + Buh(64) rows
#define SM1_SZ  (3 * ST1_SZ)     // 110592 -> 2 CTAs/SM
#define ST2_SZ  36864            // gemm2 stage: A(128) + Bh(128) rows
#define SM2_SZ  (3 * ST2_SZ)     // 110592 -> 2 CTAs/SM

// ---------------------------------------------------------------------------
// Routing + per-expert counts
// ---------------------------------------------------------------------------
__global__ void routing_kernel(const int* __restrict__ expert_index) {
    const int e    = threadIdx.x >> 5;
    const int lane = threadIdx.x & 31;
    int count = 0;
    for (int base = 0; base < TTOK; base += 32) {
        const int t = base + lane;
        const int2 ei = ((const int2*)expert_index)[t];
        int k = -1;
        if (ei.x == e) k = 0;
        else if (ei.y == e) k = 1;
        const unsigned m = __ballot_sync(0xffffffffu, k >= 0);
        if (k >= 0) {
            const int pos = count + __popc(m & ((1u << lane) - 1u));
            if (pos < CAP) {
                g_src_token[e * CAP + pos] = t;
                g_slot[t * TOPK + k] = e * CAP + pos;
            } else {
                g_slot[t * TOPK + k] = ECAP;
            }
        }
        count += __popc(m);
    }
    const int filled = count < CAP ? count : CAP;
    for (int p = filled + lane; p < CAP; p += 32)
        g_src_token[e * CAP + p] = -1;
    if (lane == 0) g_count[e] = filled;
}

// ---------------------------------------------------------------------------
// Prep: hidden states -> fp16
// ---------------------------------------------------------------------------
__global__ void split_x(const float* __restrict__ x) {
    const size_t i0 = ((size_t)blockIdx.x * 256 + threadIdx.x) * 4;
    const float4 v = *(const float4*)(x + i0);
    uint2 o;
    o.x = hpack(__float2half(v.x), __float2half(v.y));
    o.y = hpack(__float2half(v.z), __float2half(v.w));
    *(uint2*)(g_xhi + i0) = o;
}

// ---------------------------------------------------------------------------
// Prep: transposes to [e][n][k] fp16 (hi only)
// ---------------------------------------------------------------------------
__global__ void transpose_gup(const float* __restrict__ in) {
    __shared__ float tile[32][33];
    const int R = HID, C = 2 * INTERN;
    const int e  = blockIdx.z;
    const int r0 = blockIdx.y * 32, c0 = blockIdx.x * 32;
    const int tx = threadIdx.x & 31, ty = threadIdx.x >> 5;
    const size_t base = (size_t)e * R * C;
#pragma unroll
    for (int i = 0; i < 32; i += 8)
        tile[ty + i][tx] = in[base + (size_t)(r0 + ty + i) * C + c0 + tx];
    __syncthreads();
#pragma unroll
    for (int i = 0; i < 32; i += 8) {
        const float v = tile[tx][ty + i];
        g_gupT_hi[base + (size_t)(c0 + ty + i) * R + r0 + tx] = __float2half(v);
    }
}
__global__ void transpose_dp(const float* __restrict__ in) {
    __shared__ float tile[32][33];
    const int R = INTERN, C = HID;
    const int e  = blockIdx.z;
    const int r0 = blockIdx.y * 32, c0 = blockIdx.x * 32;
    const int tx = threadIdx.x & 31, ty = threadIdx.x >> 5;
    const size_t base = (size_t)e * R * C;
#pragma unroll
    for (int i = 0; i < 32; i += 8)
        tile[ty + i][tx] = in[base + (size_t)(r0 + ty + i) * C + c0 + tx];
    __syncthreads();
#pragma unroll
    for (int i = 0; i < 32; i += 8) {
        const float v = tile[tx][ty + i];
        g_dpT_hi[base + (size_t)(c0 + ty + i) * R + r0 + tx] = __float2half(v);
    }
}

// ---------------------------------------------------------------------------
// GEMM1: inter = silu(X@Wg)*(X@Wu), fp16 hi-only.
// CTA tile M=128, N=64(gate)+64(up), BK=64, single-sync 3-buffer multistage.
// 2 CTAs/SM. SMEM stage: Ah(0) Bgh(18432) Buh(27648)
// ---------------------------------------------------------------------------
__global__ __launch_bounds__(256, 2) void gemm1_mma() {
    const int e    = blockIdx.z;
    const int row0 = blockIdx.y * 128;
    if (row0 >= g_count[e]) return;          // dead-tile elimination

    extern __shared__ char smem[];
    __shared__ int s_tok[128];
    const int tid = threadIdx.x;
    const int n0  = blockIdx.x * 64;

    if (tid < 128) s_tok[tid] = g_src_token[e * CAP + row0 + tid];
    __syncthreads();
    const uint32_t sdyn = smem_u32(smem);

    auto load_stage = [&](int s, int buf) {
        const int k0 = s * 64;
        const uint32_t sd = sdyn + buf * ST1_SZ;
#pragma unroll
        for (int i = 0; i < 8; i++) {           // A hi: 128 rows x 16 cp8
            const int idx = tid + i * 256, row = idx >> 4, cc = idx & 15;
            const int tok = s_tok[row];
            const int tokc = tok < 0 ? 0 : tok;
            const uint32_t sz = tok < 0 ? 0u : 8u;
            cp8(sd + row * ROWB + cc * 8, g_xhi + (size_t)tokc * HID + k0 + cc * 4, sz);
        }
#pragma unroll
        for (int i = 0; i < 4; i++) {           // B: 64 rows x 16 cp8 x {gate,up}
            const int idx = tid + i * 256, row = idx >> 4, cc = idx & 15;
            const size_t og = ((size_t)e * 2 * INTERN + n0 + row) * HID + k0 + cc * 4;
            const size_t ou = og + (size_t)INTERN * HID;
            const uint32_t d = sd + 18432 + row * ROWB + cc * 8;
            cp8(d,        g_gupT_hi + og, 8);
            cp8(d + 9216, g_gupT_hi + ou, 8);
        }
        CP_COMMIT();
    };

    const int lane = tid & 31, wid = tid >> 5;
    const int wm = (wid & 1) * 64;
    const int wn = (wid >> 1) * 16;
    const int gq = lane >> 2, tq = lane & 3;

    float accg[4][2][4] = {}, accu[4][2][4] = {};

    const int NS = HID / 64;  // 16
    load_stage(0, 0);
    load_stage(1, 1);
    for (int s = 0; s < NS; s++) {
        if (s + 1 < NS) CP_WAIT1(); else CP_WAIT0();
        __syncthreads();
        if (s + 2 < NS) load_stage(s + 2, (s + 2) % 3);
        const int buf = s % 3;
        const uint32_t sA = sdyn + buf * ST1_SZ;
        const char*    sb = smem + buf * ST1_SZ;
#pragma unroll
        for (int ks = 0; ks < 4; ks++) {
            uint32_t ah[4][4];
#pragma unroll
            for (int i = 0; i < 4; i++) {
                const uint32_t ad = sA + (wm + i * 16 + (lane & 15)) * ROWB
                                       + (ks * 16 + ((lane >> 4) << 3)) * 2;
                ldm4(ah[i], ad);
            }
            uint32_t bg[2][2], bu[2][2];
#pragma unroll
            for (int j = 0; j < 2; j++) {
                const int boff = 18432 + (wn + j * 8 + gq) * ROWB + ks * 32 + tq * 4;
                bg[j][0] = *(const uint32_t*)(sb + boff);
                bg[j][1] = *(const uint32_t*)(sb + boff + 16);
                bu[j][0] = *(const uint32_t*)(sb + boff + 9216);
                bu[j][1] = *(const uint32_t*)(sb + boff + 9216 + 16);
            }
#pragma unroll
            for (int i = 0; i < 4; i++)
#pragma unroll
                for (int j = 0; j < 2; j++) {
                    mma_f16(accg[i][j], ah[i], bg[j]);
                    mma_f16(accu[i][j], ah[i], bu[j]);
                }
        }
    }

    // epilogue: silu(gate)*up -> fp16 direct to global
#pragma unroll
    for (int i = 0; i < 4; i++) {
        const int rg = row0 + wm + i * 16 + gq;
#pragma unroll
        for (int j = 0; j < 2; j++) {
            const int col = n0 + wn + j * 8 + 2 * tq;
#pragma unroll
            for (int h = 0; h < 2; h++) {
                const float g0 = accg[i][j][h * 2 + 0], g1 = accg[i][j][h * 2 + 1];
                const float u0 = accu[i][j][h * 2 + 0], u1 = accu[i][j][h * 2 + 1];
                const float v0 = u0 * g0 / (1.f + __expf(-g0));
                const float v1 = u1 * g1 / (1.f + __expf(-g1));
                const size_t o = ((size_t)e * CAP + rg + h * 8) * INTERN + col;
                *(uint32_t*)(g_inter_hi + o) = hpack(__float2half(v0), __float2half(v1));
            }
        }
    }
}

// ---------------------------------------------------------------------------
// GEMM2: eo = inter @ down, fp16 hi-only.
// CTA tile M=128, N=128, BK=64, single-sync 3-buffer multistage. 2 CTAs/SM.
// SMEM stage: Ah(0) Bh(18432)
// ---------------------------------------------------------------------------
__global__ __launch_bounds__(256, 2) void gemm2_mma() {
    const int e    = blockIdx.z;
    const int row0 = blockIdx.y * 128;
    if (row0 >= g_count[e]) return;          // dead-tile elimination

    extern __shared__ char smem[];
    const int tid = threadIdx.x;
    const int n0  = blockIdx.x * 128;
    const uint32_t sdyn = smem_u32(smem);

    auto load_stage = [&](int s, int buf) {
        const int k0 = s * 64;
        const uint32_t sd = sdyn + buf * ST2_SZ;
#pragma unroll
        for (int i = 0; i < 8; i++) {           // A hi: 128 rows x 16 cp8
            const int idx = tid + i * 256, row = idx >> 4, cc = idx & 15;
            const size_t oa = ((size_t)e * CAP + row0 + row) * INTERN + k0 + cc * 4;
            cp8(sd + row * ROWB + cc * 8, g_inter_hi + oa, 8);
        }
#pragma unroll
        for (int i = 0; i < 8; i++) {           // B hi: 128 rows x 16 cp8
            const int idx = tid + i * 256, row = idx >> 4, cc = idx & 15;
            const size_t ob = ((size_t)e * HID + n0 + row) * INTERN + k0 + cc * 4;
            cp8(sd + 18432 + row * ROWB + cc * 8, g_dpT_hi + ob, 8);
        }
        CP_COMMIT();
    };

    const int lane = tid & 31, wid = tid >> 5;
    const int wm = (wid & 1) * 64;
    const int wn = (wid >> 1) * 32;
    const int gq = lane >> 2, tq = lane & 3;

    float acc[4][4][4] = {};

    const int NS = INTERN / 64;  // 64
    load_stage(0, 0);
    load_stage(1, 1);
    for (int s = 0; s < NS; s++) {
        if (s + 1 < NS) CP_WAIT1(); else CP_WAIT0();
        __syncthreads();
        if (s + 2 < NS) load_stage(s + 2, (s + 2) % 3);
        const int buf = s % 3;
        const uint32_t sA = sdyn + buf * ST2_SZ;
        const char*    sb = smem + buf * ST2_SZ;
#pragma unroll
        for (int ks = 0; ks < 4; ks++) {
            uint32_t ah[4][4];
#pragma unroll
            for (int i = 0; i < 4; i++) {
                const uint32_t ad = sA + (wm + i * 16 + (lane & 15)) * ROWB
                                       + (ks * 16 + ((lane >> 4) << 3)) * 2;
                ldm4(ah[i], ad);
            }
            uint32_t bh[4][2];
#pragma unroll
            for (int j = 0; j < 4; j++) {
                const int boff = 18432 + (wn + j * 8 + gq) * ROWB + ks * 32 + tq * 4;
                bh[j][0] = *(const uint32_t*)(sb + boff);
                bh[j][1] = *(const uint32_t*)(sb + boff + 16);
            }
#pragma unroll
            for (int i = 0; i < 4; i++)
#pragma unroll
                for (int j = 0; j < 4; j++)
                    mma_f16(acc[i][j], ah[i], bh[j]);
        }
    }

#pragma unroll
    for (int i = 0; i < 4; i++) {
        const int rg = row0 + wm + i * 16 + gq;
#pragma unroll
        for (int j = 0; j < 4; j++) {
            const int col = n0 + wn + j * 8 + 2 * tq;
#pragma unroll
            for (int h = 0; h < 2; h++) {
                const size_t o = ((size_t)e * CAP + rg + h * 8) * HID + col;
                *(float2*)(g_eo + o) = make_float2(acc[i][j][h * 2], acc[i][j][h * 2 + 1]);
            }
        }
    }
}

// ---------------------------------------------------------------------------
// Combine (verified R1)
// ---------------------------------------------------------------------------
__global__ void combine_kernel(const float* __restrict__ aff,
                               const int*   __restrict__ eidx,
                               float*       __restrict__ out) {
    const int idx = blockIdx.x * 256 + threadIdx.x;
    const int t = idx >> 8;
    const int c = (idx & 255) << 2;
    const int2 ei = ((const int2*)eidx)[t];
    const float a0 = aff[t * NE + ei.x];
    const float a1 = aff[t * NE + ei.y];
    const float inv = 1.f / (a0 + a1);
    const int s0 = g_slot[t * TOPK + 0];
    const int s1 = g_slot[t * TOPK + 1];
    float4 r = make_float4(0.f, 0.f, 0.f, 0.f);
    if (s0 < ECAP) {
        const float w = a0 * inv;
        const float4 v = *(const float4*)(g_eo + (size_t)s0 * HID + c);
        r.x += w * v.x; r.y += w * v.y; r.z += w * v.z; r.w += w * v.w;
    }
    if (s1 < ECAP) {
        const float w = a1 * inv;
        const float4 v = *(const float4*)(g_eo + (size_t)s1 * HID + c);
        r.x += w * v.x; r.y += w * v.y; r.z += w * v.z; r.w += w * v.w;
    }
    *(float4*)(out + (size_t)t * HID + c) = r;
}

// ---------------------------------------------------------------------------
extern "C" void kernel_launch(void* const* d_in, const int* in_sizes, int n_in,
                              void* d_out, int out_size) {
    const float* x    = (const float*)d_in[0];
    const float* aff  = (const float*)d_in[1];
    const int*   eidx = (const int*)  d_in[2];
    const float* gup  = (const float*)d_in[3];
    const float* dp   = (const float*)d_in[4];
    float* out = (float*)d_out;

    cudaFuncSetAttribute(gemm1_mma, cudaFuncAttributeMaxDynamicSharedMemorySize, SM1_SZ);
    cudaFuncSetAttribute(gemm2_mma, cudaFuncAttributeMaxDynamicSharedMemorySize, SM2_SZ);

    routing_kernel<<<1, 256>>>(eidx);
    split_x<<<(TTOK * HID) / 1024, 256>>>(x);
    transpose_gup<<<dim3(2 * INTERN / 32, HID / 32, NE), 256>>>(gup);
    transpose_dp<<<dim3(HID / 32, INTERN / 32, NE), 256>>>(dp);
    gemm1_mma<<<dim3(INTERN / 64, CAP / 128, NE), 256, SM1_SZ>>>();
    gemm2_mma<<<dim3(HID / 128, CAP / 128, NE), 256, SM2_SZ>>>();
    combine_kernel<<<(TTOK * (HID / 4)) / 256, 256>>>(aff, eidx, out);
}

// round 13
// speedup vs baseline: 1.0082x; 1.0002x over previous
#include <cuda_runtime.h>
#include <cuda_fp16.h>
#include <math.h>
#include <stdint.h>

#define NE      8
#define TOPK    2
#define HID     1024
#define INTERN  4096
#define TTOK    8192
#define CAP     2560
#define ECAP    (NE*CAP)

// ---------------- scratch (static device globals) ----------------
__device__ int      g_src_token[ECAP];
__device__ int      g_slot[TTOK * TOPK];
__device__ int      g_count[NE];
__device__ __half   g_xhi[(size_t)TTOK * HID];
__device__ __half   g_gupT_hi[(size_t)NE * 2 * INTERN * HID];  // [e][n][k]
__device__ __half   g_dpT_hi[(size_t)NE * HID * INTERN];       // [e][n][k]
__device__ __half   g_inter_hi[(size_t)ECAP * INTERN];
__device__ float    g_eo[(size_t)ECAP * HID];

// ---------------- helpers ----------------
__device__ __forceinline__ uint32_t smem_u32(const void* p) {
    uint32_t a;
    asm("{ .reg .u64 t; cvta.to.shared.u64 t, %1; cvt.u32.u64 %0, t; }" : "=r"(a) : "l"(p));
    return a;
}
__device__ __forceinline__ void mma_f16(float* d, const uint32_t* a, const uint32_t* b) {
    asm volatile(
        "mma.sync.aligned.m16n8k16.row.col.f32.f16.f16.f32 "
        "{%0,%1,%2,%3}, {%4,%5,%6,%7}, {%8,%9}, {%0,%1,%2,%3};"
        : "+f"(d[0]), "+f"(d[1]), "+f"(d[2]), "+f"(d[3])
        : "r"(a[0]), "r"(a[1]), "r"(a[2]), "r"(a[3]), "r"(b[0]), "r"(b[1]));
}
__device__ __forceinline__ void ldm4(uint32_t* r, uint32_t addr) {
    asm volatile("ldmatrix.sync.aligned.m8n8.x4.shared.b16 {%0,%1,%2,%3}, [%4];"
        : "=r"(r[0]), "=r"(r[1]), "=r"(r[2]), "=r"(r[3]) : "r"(addr));
}
__device__ __forceinline__ void cp8(uint32_t dst, const void* src, uint32_t sz) {
    asm volatile("cp.async.ca.shared.global [%0], [%1], 8, %2;"
        :: "r"(dst), "l"(src), "r"(sz) : "memory");
}
#define CP_COMMIT() asm volatile("cp.async.commit_group;" ::: "memory")
#define CP_WAIT1()  asm volatile("cp.async.wait_group 1;" ::: "memory")
#define CP_WAIT0()  asm volatile("cp.async.wait_group 0;" ::: "memory")

__device__ __forceinline__ uint32_t hpack(__half a, __half b) {
    return (uint32_t)__half_as_ushort(a) | ((uint32_t)__half_as_ushort(b) << 16);
}

// SMEM geometry: rows padded to 72 halves (144B), conflict-free (verified R3-R8).
#define ROWB    144
#define ST1_SZ  36864            // gemm1 stage: A(128) + Bgh(64) + Buh(64) rows
#define SM1_SZ  (3 * ST1_SZ)     // 110592 -> 2 CTAs/SM
#define ST2_SZ  36864            // gemm2 stage: A(128) + Bh(128) rows
#define SM2_SZ  (3 * ST2_SZ)     // 110592 -> 2 CTAs/SM

// ---------------------------------------------------------------------------
// Routing + per-expert counts
// ---------------------------------------------------------------------------
__global__ void routing_kernel(const int* __restrict__ expert_index) {
    const int e    = threadIdx.x >> 5;
    const int lane = threadIdx.x & 31;
    int count = 0;
    for (int base = 0; base < TTOK; base += 32) {
        const int t = base + lane;
        const int2 ei = ((const int2*)expert_index)[t];
        int k = -1;
        if (ei.x == e) k = 0;
        else if (ei.y == e) k = 1;
        const unsigned m = __ballot_sync(0xffffffffu, k >= 0);
        if (k >= 0) {
            const int pos = count + __popc(m & ((1u << lane) - 1u));
            if (pos < CAP) {
                g_src_token[e * CAP + pos] = t;
                g_slot[t * TOPK + k] = e * CAP + pos;
            } else {
                g_slot[t * TOPK + k] = ECAP;
            }
        }
        count += __popc(m);
    }
    const int filled = count < CAP ? count : CAP;
    for (int p = filled + lane; p < CAP; p += 32)
        g_src_token[e * CAP + p] = -1;
    if (lane == 0) g_count[e] = filled;
}

// ---------------------------------------------------------------------------
// Prep: hidden states -> fp16
// ---------------------------------------------------------------------------
__global__ void split_x(const float* __restrict__ x) {
    const size_t i0 = ((size_t)blockIdx.x * 256 + threadIdx.x) * 4;
    const float4 v = *(const float4*)(x + i0);
    uint2 o;
    o.x = hpack(__float2half(v.x), __float2half(v.y));
    o.y = hpack(__float2half(v.z), __float2half(v.w));
    *(uint2*)(g_xhi + i0) = o;
}

// ---------------------------------------------------------------------------
// Prep: transposes to [e][n][k] fp16 (hi only)
// ---------------------------------------------------------------------------
__global__ void transpose_gup(const float* __restrict__ in) {
    __shared__ float tile[32][33];
    const int R = HID, C = 2 * INTERN;
    const int e  = blockIdx.z;
    const int r0 = blockIdx.y * 32, c0 = blockIdx.x * 32;
    const int tx = threadIdx.x & 31, ty = threadIdx.x >> 5;
    const size_t base = (size_t)e * R * C;
#pragma unroll
    for (int i = 0; i < 32; i += 8)
        tile[ty + i][tx] = in[base + (size_t)(r0 + ty + i) * C + c0 + tx];
    __syncthreads();
#pragma unroll
    for (int i = 0; i < 32; i += 8) {
        const float v = tile[tx][ty + i];
        g_gupT_hi[base + (size_t)(c0 + ty + i) * R + r0 + tx] = __float2half(v);
    }
}
__global__ void transpose_dp(const float* __restrict__ in) {
    __shared__ float tile[32][33];
    const int R = INTERN, C = HID;
    const int e  = blockIdx.z;
    const int r0 = blockIdx.y * 32, c0 = blockIdx.x * 32;
    const int tx = threadIdx.x & 31, ty = threadIdx.x >> 5;
    const size_t base = (size_t)e * R * C;
#pragma unroll
    for (int i = 0; i < 32; i += 8)
        tile[ty + i][tx] = in[base + (size_t)(r0 + ty + i) * C + c0 + tx];
    __syncthreads();
#pragma unroll
    for (int i = 0; i < 32; i += 8) {
        const float v = tile[tx][ty + i];
        g_dpT_hi[base + (size_t)(c0 + ty + i) * R + r0 + tx] = __float2half(v);
    }
}

// ---------------------------------------------------------------------------
// GEMM1: inter = silu(X@Wg)*(X@Wu), fp16 hi-only.
// CTA tile M=128, N=64(gate)+64(up), BK=64, single-sync 3-buffer multistage.
// 2 CTAs/SM. SMEM stage: Ah(0) Bgh(18432) Buh(27648)
// ---------------------------------------------------------------------------
__global__ __launch_bounds__(256, 2) void gemm1_mma() {
    const int e    = blockIdx.z;
    const int row0 = blockIdx.y * 128;
    if (row0 >= g_count[e]) return;          // dead-tile elimination

    extern __shared__ char smem[];
    __shared__ int s_tok[128];
    const int tid = threadIdx.x;
    const int n0  = blockIdx.x * 64;

    if (tid < 128) s_tok[tid] = g_src_token[e * CAP + row0 + tid];
    __syncthreads();
    const uint32_t sdyn = smem_u32(smem);

    auto load_stage = [&](int s, int buf) {
        const int k0 = s * 64;
        const uint32_t sd = sdyn + buf * ST1_SZ;
#pragma unroll
        for (int i = 0; i < 8; i++) {           // A hi: 128 rows x 16 cp8
            const int idx = tid + i * 256, row = idx >> 4, cc = idx & 15;
            const int tok = s_tok[row];
            const int tokc = tok < 0 ? 0 : tok;
            const uint32_t sz = tok < 0 ? 0u : 8u;
            cp8(sd + row * ROWB + cc * 8, g_xhi + (size_t)tokc * HID + k0 + cc * 4, sz);
        }
#pragma unroll
        for (int i = 0; i < 4; i++) {           // B: 64 rows x 16 cp8 x {gate,up}
            const int idx = tid + i * 256, row = idx >> 4, cc = idx & 15;
            const size_t og = ((size_t)e * 2 * INTERN + n0 + row) * HID + k0 + cc * 4;
            const size_t ou = og + (size_t)INTERN * HID;
            const uint32_t d = sd + 18432 + row * ROWB + cc * 8;
            cp8(d,        g_gupT_hi + og, 8);
            cp8(d + 9216, g_gupT_hi + ou, 8);
        }
        CP_COMMIT();
    };

    const int lane = tid & 31, wid = tid >> 5;
    const int wm = (wid & 1) * 64;
    const int wn = (wid >> 1) * 16;
    const int gq = lane >> 2, tq = lane & 3;

    float accg[4][2][4] = {}, accu[4][2][4] = {};

    const int NS = HID / 64;  // 16
    load_stage(0, 0);
    load_stage(1, 1);
    for (int s = 0; s < NS; s++) {
        if (s + 1 < NS) CP_WAIT1(); else CP_WAIT0();
        __syncthreads();
        if (s + 2 < NS) load_stage(s + 2, (s + 2) % 3);
        const int buf = s % 3;
        const uint32_t sA = sdyn + buf * ST1_SZ;
        const char*    sb = smem + buf * ST1_SZ;
#pragma unroll
        for (int ks = 0; ks < 4; ks++) {
            uint32_t ah[4][4];
#pragma unroll
            for (int i = 0; i < 4; i++) {
                const uint32_t ad = sA + (wm + i * 16 + (lane & 15)) * ROWB
                                       + (ks * 16 + ((lane >> 4) << 3)) * 2;
                ldm4(ah[i], ad);
            }
            uint32_t bg[2][2], bu[2][2];
#pragma unroll
            for (int j = 0; j < 2; j++) {
                const int boff = 18432 + (wn + j * 8 + gq) * ROWB + ks * 32 + tq * 4;
                bg[j][0] = *(const uint32_t*)(sb + boff);
                bg[j][1] = *(const uint32_t*)(sb + boff + 16);
                bu[j][0] = *(const uint32_t*)(sb + boff + 9216);
                bu[j][1] = *(const uint32_t*)(sb + boff + 9216 + 16);
            }
#pragma unroll
            for (int i = 0; i < 4; i++)
#pragma unroll
                for (int j = 0; j < 2; j++) {
                    mma_f16(accg[i][j], ah[i], bg[j]);
                    mma_f16(accu[i][j], ah[i], bu[j]);
                }
        }
    }

    // epilogue: silu(gate)*up -> fp16 direct to global
#pragma unroll
    for (int i = 0; i < 4; i++) {
        const int rg = row0 + wm + i * 16 + gq;
#pragma unroll
        for (int j = 0; j < 2; j++) {
            const int col = n0 + wn + j * 8 + 2 * tq;
#pragma unroll
            for (int h = 0; h < 2; h++) {
                const float g0 = accg[i][j][h * 2 + 0], g1 = accg[i][j][h * 2 + 1];
                const float u0 = accu[i][j][h * 2 + 0], u1 = accu[i][j][h * 2 + 1];
                const float v0 = u0 * g0 / (1.f + __expf(-g0));
                const float v1 = u1 * g1 / (1.f + __expf(-g1));
                const size_t o = ((size_t)e * CAP + rg + h * 8) * INTERN + col;
                *(uint32_t*)(g_inter_hi + o) = hpack(__float2half(v0), __float2half(v1));
            }
        }
    }
}

// ---------------------------------------------------------------------------
// GEMM2: eo = inter @ down, fp16 hi-only.
// CTA tile M=128, N=128, BK=64, single-sync 3-buffer multistage. 2 CTAs/SM.
// SMEM stage: Ah(0) Bh(18432)
// ---------------------------------------------------------------------------
__global__ __launch_bounds__(256, 2) void gemm2_mma() {
    const int e    = blockIdx.z;
    const int row0 = blockIdx.y * 128;
    if (row0 >= g_count[e]) return;          // dead-tile elimination

    extern __shared__ char smem[];
    const int tid = threadIdx.x;
    const int n0  = blockIdx.x * 128;
    const uint32_t sdyn = smem_u32(smem);

    auto load_stage = [&](int s, int buf) {
        const int k0 = s * 64;
        const uint32_t sd = sdyn + buf * ST2_SZ;
#pragma unroll
        for (int i = 0; i < 8; i++) {           // A hi: 128 rows x 16 cp8
            const int idx = tid + i * 256, row = idx >> 4, cc = idx & 15;
            const size_t oa = ((size_t)e * CAP + row0 + row) * INTERN + k0 + cc * 4;
            cp8(sd + row * ROWB + cc * 8, g_inter_hi + oa, 8);
        }
#pragma unroll
        for (int i = 0; i < 8; i++) {           // B hi: 128 rows x 16 cp8
            const int idx = tid + i * 256, row = idx >> 4, cc = idx & 15;
            const size_t ob = ((size_t)e * HID + n0 + row) * INTERN + k0 + cc * 4;
            cp8(sd + 18432 + row * ROWB + cc * 8, g_dpT_hi + ob, 8);
        }
        CP_COMMIT();
    };

    const int lane = tid & 31, wid = tid >> 5;
    const int wm = (wid & 1) * 64;
    const int wn = (wid >> 1) * 32;
    const int gq = lane >> 2, tq = lane & 3;

    float acc[4][4][4] = {};

    const int NS = INTERN / 64;  // 64
    load_stage(0, 0);
    load_stage(1, 1);
    for (int s = 0; s < NS; s++) {
        if (s + 1 < NS) CP_WAIT1(); else CP_WAIT0();
        __syncthreads();
        if (s + 2 < NS) load_stage(s + 2, (s + 2) % 3);
        const int buf = s % 3;
        const uint32_t sA = sdyn + buf * ST2_SZ;
        const char*    sb = smem + buf * ST2_SZ;
#pragma unroll
        for (int ks = 0; ks < 4; ks++) {
            uint32_t ah[4][4];
#pragma unroll
            for (int i = 0; i < 4; i++) {
                const uint32_t ad = sA + (wm + i * 16 + (lane & 15)) * ROWB
                                       + (ks * 16 + ((lane >> 4) << 3)) * 2;
                ldm4(ah[i], ad);
            }
            uint32_t bh[4][2];
#pragma unroll
            for (int j = 0; j < 4; j++) {
                const int boff = 18432 + (wn + j * 8 + gq) * ROWB + ks * 32 + tq * 4;
                bh[j][0] = *(const uint32_t*)(sb + boff);
                bh[j][1] = *(const uint32_t*)(sb + boff + 16);
            }
#pragma unroll
            for (int i = 0; i < 4; i++)
#pragma unroll
                for (int j = 0; j < 4; j++)
                    mma_f16(acc[i][j], ah[i], bh[j]);
        }
    }

#pragma unroll
    for (int i = 0; i < 4; i++) {
        const int rg = row0 + wm + i * 16 + gq;
#pragma unroll
        for (int j = 0; j < 4; j++) {
            const int col = n0 + wn + j * 8 + 2 * tq;
#pragma unroll
            for (int h = 0; h < 2; h++) {
                const size_t o = ((size_t)e * CAP + rg + h * 8) * HID + col;
                *(float2*)(g_eo + o) = make_float2(acc[i][j][h * 2], acc[i][j][h * 2 + 1]);
            }
        }
    }
}

// ---------------------------------------------------------------------------
// Combine (verified R1)
// ---------------------------------------------------------------------------
__global__ void combine_kernel(const float* __restrict__ aff,
                               const int*   __restrict__ eidx,
                               float*       __restrict__ out) {
    const int idx = blockIdx.x * 256 + threadIdx.x;
    const int t = idx >> 8;
    const int c = (idx & 255) << 2;
    const int2 ei = ((const int2*)eidx)[t];
    const float a0 = aff[t * NE + ei.x];
    const float a1 = aff[t * NE + ei.y];
    const float inv = 1.f / (a0 + a1);
    const int s0 = g_slot[t * TOPK + 0];
    const int s1 = g_slot[t * TOPK + 1];
    float4 r = make_float4(0.f, 0.f, 0.f, 0.f);
    if (s0 < ECAP) {
        const float w = a0 * inv;
        const float4 v = *(const float4*)(g_eo + (size_t)s0 * HID + c);
        r.x += w * v.x; r.y += w * v.y; r.z += w * v.z; r.w += w * v.w;
    }
    if (s1 < ECAP) {
        const float w = a1 * inv;
        const float4 v = *(const float4*)(g_eo + (size_t)s1 * HID + c);
        r.x += w * v.x; r.y += w * v.y; r.z += w * v.z; r.w += w * v.w;
    }
    *(float4*)(out + (size_t)t * HID + c) = r;
}

// ---------------------------------------------------------------------------
extern "C" void kernel_launch(void* const* d_in, const int* in_sizes, int n_in,
                              void* d_out, int out_size) {
    const float* x    = (const float*)d_in[0];
    const float* aff  = (const float*)d_in[1];
    const int*   eidx = (const int*)  d_in[2];
    const float* gup  = (const float*)d_in[3];
    const float* dp   = (const float*)d_in[4];
    float* out = (float*)d_out;

    cudaFuncSetAttribute(gemm1_mma, cudaFuncAttributeMaxDynamicSharedMemorySize, SM1_SZ);
    cudaFuncSetAttribute(gemm2_mma, cudaFuncAttributeMaxDynamicSharedMemorySize, SM2_SZ);

    routing_kernel<<<1, 256>>>(eidx);
    split_x<<<(TTOK * HID) / 1024, 256>>>(x);
    transpose_gup<<<dim3(2 * INTERN / 32, HID / 32, NE), 256>>>(gup);
    transpose_dp<<<dim3(HID / 32, INTERN / 32, NE), 256>>>(dp);
    gemm1_mma<<<dim3(INTERN / 64, CAP / 128, NE), 256, SM1_SZ>>>();
    gemm2_mma<<<dim3(HID / 128, CAP / 128, NE), 256, SM2_SZ>>>();
    combine_kernel<<<(TTOK * (HID / 4)) / 256, 256>>>(aff, eidx, out);
}